// round 8
// baseline (speedup 1.0000x reference)
#include <cuda_runtime.h>

#define N_BINS 10
#define GRID_BLOCKS 888     // 148 SMs * 6 blocks -> one wave
#define BLOCK_THREADS 256
#define TOTAL_WARPS (GRID_BLOCKS * (BLOCK_THREADS / 32))

// Global scratch (no allocations allowed). Zero-initialized at module load;
// the last finishing block resets them, so "zeroed at entry" holds across
// graph replays.
__device__ double g_cnt[N_BINS];
__device__ double g_conf[N_BINS];
__device__ double g_acc[N_BINS];
__device__ unsigned g_done;

__device__ __forceinline__ float ex2(float x) {
    float r;
    asm("ex2.approx.f32 %0, %1;" : "=f"(r) : "f"(x));
    return r;
}

// Two rows per warp: lanes 0-15 handle one row, lanes 16-31 the next, via
// partitioned redux/shfl. Each lane holds 8 columns of its row:
// cols 4*hl..4*hl+3 (A) and 64+4*hl..64+4*hl+3 (B).
// lab = label of THIS lane's row. mask = this half's partition mask.
// Lane hl of each half accumulates bin hl.
__device__ __forceinline__ void ece_pair(
    float4 A, float4 B, int lab, unsigned mask, int hl, int half,
    bool acc_en,
    float& r_cnt, float& r_conf, float& r_acc)
{
    const float L2E = 1.4426950408889634f;
    // 65536*exp(x) = 2^(x*log2e + 16); keeps sum+max consistently scaled.
    float e0 = ex2(fmaf(A.x, L2E, 16.0f));
    float e1 = ex2(fmaf(A.y, L2E, 16.0f));
    float e2 = ex2(fmaf(A.z, L2E, 16.0f));
    float e3 = ex2(fmaf(A.w, L2E, 16.0f));
    float e4 = ex2(fmaf(B.x, L2E, 16.0f));
    float e5 = ex2(fmaf(B.y, L2E, 16.0f));
    float e6 = ex2(fmaf(B.z, L2E, 16.0f));
    float e7 = ex2(fmaf(B.w, L2E, 16.0f));

    float s = ((e0 + e1) + (e2 + e3)) + ((e4 + e5) + (e6 + e7));
    unsigned usum = __reduce_add_sync(mask, __float2uint_rn(s));

    float m = fmaxf(fmaxf(fmaxf(e0, e1), fmaxf(e2, e3)),
                    fmaxf(fmaxf(e4, e5), fmaxf(e6, e7)));
    unsigned wk = __reduce_max_sync(mask, __float_as_uint(m));  // exps > 0
    float wm = __uint_as_float(wk);

    // Scaled exp at the label column, selected in EXP domain (matches wm),
    // fetched from its owner lane within this half.
    int sub = lab & 3;
    float elo = (sub & 2) ? ((sub & 1) ? e3 : e2) : ((sub & 1) ? e1 : e0);
    float ehi = (sub & 2) ? ((sub & 1) ? e7 : e6) : ((sub & 1) ? e5 : e4);
    float cv  = (lab & 64) ? ehi : elo;
    float vL  = __shfl_sync(0xffffffffu, cv, (half << 4) | ((lab >> 2) & 15));

    float conf = __fdividef(wm, __uint2float_rn(usum));   // max prob
    int b1 = min((int)ceilf(conf * 10.0f), N_BINS);       // in [1,10]
    if (acc_en && b1 == hl + 1) {
        r_cnt  += 1.0f;
        r_conf += conf;
        r_acc  += (vL == wm) ? 1.0f : 0.0f;
    }
}

__global__ void __launch_bounds__(BLOCK_THREADS, 6) ece_fused(
    const float* __restrict__ logits,
    const int* __restrict__ labels,
    int n_rows,
    float* __restrict__ out)
{
    __shared__ float s_c[N_BINS], s_f[N_BINS], s_a[N_BINS];

    int tid = threadIdx.x;
    if (tid < N_BINS) { s_c[tid] = 0.0f; s_f[tid] = 0.0f; s_a[tid] = 0.0f; }

    const int lane  = tid & 31;
    const int half  = lane >> 4;           // 0: even row of pair, 1: odd row
    const int hl    = lane & 15;
    const unsigned mask = 0xFFFFu << (half << 4);
    const int warp  = tid >> 5;
    const int gwarp = blockIdx.x * (BLOCK_THREADS / 32) + warp;

    const float4* __restrict__ lrows = (const float4*)logits;

    float r_cnt = 0.0f, r_conf = 0.0f, r_acc = 0.0f;

    // Pair-granular software pipeline: prefetch next pair while computing cur.
    const int n_pairs = n_rows >> 1;
    int iters = (gwarp < n_pairs) ? (n_pairs - 1 - gwarp) / TOTAL_WARPS + 1 : 0;

    const float4* __restrict__ p  = lrows + (size_t)gwarp * 64 + (half << 5) + hl;
    const int2*   __restrict__ lp = (const int2*)labels + gwarp;

    if (iters > 0) {
        float4 A = __ldcs(p);
        float4 B = __ldcs(p + 16);
        int2   L = *lp;
        #pragma unroll 2
        for (int i = 1; i < iters; i++) {
            p  += (size_t)TOTAL_WARPS * 64;
            lp += TOTAL_WARPS;
            float4 A2 = __ldcs(p);          // prefetch iter i
            float4 B2 = __ldcs(p + 16);
            int2   L2 = *lp;
            ece_pair(A, B, half ? L.y : L.x, mask, hl, half, true,
                     r_cnt, r_conf, r_acc);
            A = A2; B = B2; L = L2;
        }
        ece_pair(A, B, half ? L.y : L.x, mask, hl, half, true,
                 r_cnt, r_conf, r_acc);
    }

    // Odd leftover row (n_rows odd): warp 0 handles it, halves mirror the row.
    if (gwarp == 0) {
        for (int r = n_pairs * 2; r < n_rows; r++) {
            const float4* q = lrows + (size_t)r * 32 + hl;
            float4 A = q[0], B = q[16];
            ece_pair(A, B, labels[r], mask, hl, half, half == 0,
                     r_cnt, r_conf, r_acc);
        }
    }

    // Block reduction: lane hl (<10) of each half holds bin hl partials.
    __syncthreads();                   // also covers the s_* zero-init
    if (hl < N_BINS) {
        atomicAdd(&s_c[hl], r_cnt);
        atomicAdd(&s_f[hl], r_conf);
        atomicAdd(&s_a[hl], r_acc);
    }
    __syncthreads();

    if (tid < N_BINS) {
        atomicAdd(&g_cnt[tid],  (double)s_c[tid]);
        atomicAdd(&g_conf[tid], (double)s_f[tid]);
        atomicAdd(&g_acc[tid],  (double)s_a[tid]);
        __threadfence();               // order bin atomics before done-ticket
    }
    __syncthreads();

    // Last block finalizes and resets scratch for the next graph replay.
    if (tid == 0) {
        unsigned ticket = atomicAdd(&g_done, 1u);
        if (ticket == GRID_BLOCKS - 1) {
            double ece = 0.0, oe = 0.0;
            #pragma unroll
            for (int i = 0; i < N_BINS; i++) {
                double cnt = atomicAdd(&g_cnt[i],  0.0);
                double cf  = atomicAdd(&g_conf[i], 0.0);
                double ac  = atomicAdd(&g_acc[i],  0.0);
                bool nonempty = cnt > 0.0;
                double prop  = cnt / (double)n_rows;
                double denom = nonempty ? cnt : 1.0;
                double accb  = nonempty ? ac / denom : 0.0;
                double cfb   = nonempty ? cf / denom : 0.0;
                double CE    = cfb - accb;
                double absCE = nonempty ? fabs(CE) : 0.0;
                ece += absCE * prop;
                oe  += (nonempty ? cfb * fmax(CE, 0.0) : 0.0) * prop;
                out[1 + i]  = (float)accb;
                out[12 + i] = (float)prop;
                out[22 + i] = (float)absCE;
                g_cnt[i] = 0.0; g_conf[i] = 0.0; g_acc[i] = 0.0;
            }
            out[0]  = (float)ece;
            out[11] = (float)oe;
            g_done = 0u;
            __threadfence();
        }
    }
}

extern "C" void kernel_launch(void* const* d_in, const int* in_sizes, int n_in,
                              void* d_out, int out_size) {
    const float* logits = (const float*)d_in[0];
    const int*   labels = (const int*)d_in[1];
    float*       out    = (float*)d_out;

    int n_rows = in_sizes[0] / 128;   // C = 128

    ece_fused<<<GRID_BLOCKS, BLOCK_THREADS>>>(logits, labels, n_rows, out);
}

// round 9
// speedup vs baseline: 1.0217x; 1.0217x over previous
#include <cuda_runtime.h>

#define N_BINS 10
#define GRID_BLOCKS 1184    // 148 SMs * 8 blocks -> one wave at full occupancy
#define BLOCK_THREADS 256
#define TOTAL_WARPS (GRID_BLOCKS * (BLOCK_THREADS / 32))

// Global scratch (no allocations allowed). Zero-initialized at module load;
// the last finishing block resets them, so "zeroed at entry" holds across
// graph replays.
__device__ double g_cnt[N_BINS];
__device__ double g_conf[N_BINS];
__device__ double g_acc[N_BINS];
__device__ unsigned g_done;

__device__ __forceinline__ float ex2(float x) {
    float r;
    asm("ex2.approx.f32 %0, %1;" : "=f"(r) : "f"(x));
    return r;
}

// Two rows per warp: lanes 0-15 handle one row, lanes 16-31 the next, via
// partitioned redux. Each lane holds 8 columns of its row:
// cols 4*hl..4*hl+3 (A) and 64+4*hl..64+4*hl+3 (B).
// lab = label of THIS lane's row (same across the half). mask = half's mask.
// Lane hl of each half accumulates bin hl.
__device__ __forceinline__ void ece_pair(
    float4 A, float4 B, int lab, unsigned mask, int hl,
    bool acc_en,
    float& r_cnt, float& r_conf, float& r_acc)
{
    const float L2E = 1.4426950408889634f;
    // 65536*exp(x) = 2^(x*log2e + 16); keeps sum+max consistently scaled.
    float e0 = ex2(fmaf(A.x, L2E, 16.0f));
    float e1 = ex2(fmaf(A.y, L2E, 16.0f));
    float e2 = ex2(fmaf(A.z, L2E, 16.0f));
    float e3 = ex2(fmaf(A.w, L2E, 16.0f));
    float e4 = ex2(fmaf(B.x, L2E, 16.0f));
    float e5 = ex2(fmaf(B.y, L2E, 16.0f));
    float e6 = ex2(fmaf(B.z, L2E, 16.0f));
    float e7 = ex2(fmaf(B.w, L2E, 16.0f));

    float s = ((e0 + e1) + (e2 + e3)) + ((e4 + e5) + (e6 + e7));
    unsigned usum = __reduce_add_sync(mask, __float2uint_rn(s));

    float m = fmaxf(fmaxf(fmaxf(e0, e1), fmaxf(e2, e3)),
                    fmaxf(fmaxf(e4, e5), fmaxf(e6, e7)));

    // Does MY lane own the label column, and does that column attain my
    // local max? (Selected in EXP domain — same domain as m.)
    int sub = lab & 3;
    float elo = (sub & 2) ? ((sub & 1) ? e3 : e2) : ((sub & 1) ? e1 : e0);
    float ehi = (sub & 2) ? ((sub & 1) ? e7 : e6) : ((sub & 1) ? e5 : e4);
    float vl  = (lab & 64) ? ehi : elo;
    unsigned bit = (((lab >> 2) & 15) == hl) && (vl == m);

    // Packed key: scaled exps are positive and < 2^31 as bits, so
    // (bits<<1)|correct is order-preserving in m. One REDUX gives the half's
    // max AND whether the winning value sits at the label column.
    unsigned wk = __reduce_max_sync(mask, (__float_as_uint(m) << 1) | bit);
    float wm = __uint_as_float(wk >> 1);

    float conf = __fdividef(wm, __uint2float_rn(usum));   // max prob
    int b1 = min((int)ceilf(conf * 10.0f), N_BINS);       // in [1,10]
    if (acc_en && b1 == hl + 1) {
        r_cnt  += 1.0f;
        r_conf += conf;
        r_acc  += (float)(wk & 1u);
    }
}

__global__ void __launch_bounds__(BLOCK_THREADS, 8) ece_fused(
    const float* __restrict__ logits,
    const int* __restrict__ labels,
    int n_rows,
    float* __restrict__ out)
{
    __shared__ float s_c[N_BINS], s_f[N_BINS], s_a[N_BINS];

    int tid = threadIdx.x;
    if (tid < N_BINS) { s_c[tid] = 0.0f; s_f[tid] = 0.0f; s_a[tid] = 0.0f; }

    const int lane  = tid & 31;
    const int half  = lane >> 4;           // 0: even row of pair, 1: odd row
    const int hl    = lane & 15;
    const unsigned mask = 0xFFFFu << (half << 4);
    const int warp  = tid >> 5;
    const int gwarp = blockIdx.x * (BLOCK_THREADS / 32) + warp;

    const float4* __restrict__ lrows = (const float4*)logits;

    float r_cnt = 0.0f, r_conf = 0.0f, r_acc = 0.0f;

    // One pair (2 rows = 1KB) per iteration; rely on 64-warp TLP for latency.
    const int n_pairs = n_rows >> 1;
    const float4* __restrict__ p = lrows + (size_t)gwarp * 64 + (half << 5) + hl;
    const int2*   __restrict__ lp = (const int2*)labels + gwarp;

    #pragma unroll 1
    for (int pr = gwarp; pr < n_pairs; pr += TOTAL_WARPS) {
        float4 A = p[0];
        float4 B = p[16];
        int2   L = *lp;
        ece_pair(A, B, half ? L.y : L.x, mask, hl, true,
                 r_cnt, r_conf, r_acc);
        p  += (size_t)TOTAL_WARPS * 64;
        lp += TOTAL_WARPS;
    }

    // Odd leftover row (n_rows odd): warp 0 handles it, halves mirror the row.
    if (gwarp == 0) {
        for (int r = n_pairs * 2; r < n_rows; r++) {
            const float4* q = lrows + (size_t)r * 32 + hl;
            float4 A = q[0], B = q[16];
            ece_pair(A, B, labels[r], mask, hl, half == 0,
                     r_cnt, r_conf, r_acc);
        }
    }

    // Block reduction: lane hl (<10) of each half holds bin hl partials.
    __syncthreads();                   // also covers the s_* zero-init
    if (hl < N_BINS) {
        atomicAdd(&s_c[hl], r_cnt);
        atomicAdd(&s_f[hl], r_conf);
        atomicAdd(&s_a[hl], r_acc);
    }
    __syncthreads();

    if (tid < N_BINS) {
        atomicAdd(&g_cnt[tid],  (double)s_c[tid]);
        atomicAdd(&g_conf[tid], (double)s_f[tid]);
        atomicAdd(&g_acc[tid],  (double)s_a[tid]);
        __threadfence();               // order bin atomics before done-ticket
    }
    __syncthreads();

    // Last block finalizes and resets scratch for the next graph replay.
    if (tid == 0) {
        unsigned ticket = atomicAdd(&g_done, 1u);
        if (ticket == GRID_BLOCKS - 1) {
            double ece = 0.0, oe = 0.0;
            #pragma unroll
            for (int i = 0; i < N_BINS; i++) {
                double cnt = atomicAdd(&g_cnt[i],  0.0);
                double cf  = atomicAdd(&g_conf[i], 0.0);
                double ac  = atomicAdd(&g_acc[i],  0.0);
                bool nonempty = cnt > 0.0;
                double prop  = cnt / (double)n_rows;
                double denom = nonempty ? cnt : 1.0;
                double accb  = nonempty ? ac / denom : 0.0;
                double cfb   = nonempty ? cf / denom : 0.0;
                double CE    = cfb - accb;
                double absCE = nonempty ? fabs(CE) : 0.0;
                ece += absCE * prop;
                oe  += (nonempty ? cfb * fmax(CE, 0.0) : 0.0) * prop;
                out[1 + i]  = (float)accb;
                out[12 + i] = (float)prop;
                out[22 + i] = (float)absCE;
                g_cnt[i] = 0.0; g_conf[i] = 0.0; g_acc[i] = 0.0;
            }
            out[0]  = (float)ece;
            out[11] = (float)oe;
            g_done = 0u;
            __threadfence();
        }
    }
}

extern "C" void kernel_launch(void* const* d_in, const int* in_sizes, int n_in,
                              void* d_out, int out_size) {
    const float* logits = (const float*)d_in[0];
    const int*   labels = (const int*)d_in[1];
    float*       out    = (float*)d_out;

    int n_rows = in_sizes[0] / 128;   // C = 128

    ece_fused<<<GRID_BLOCKS, BLOCK_THREADS>>>(logits, labels, n_rows, out);
}